// round 3
// baseline (speedup 1.0000x reference)
#include <cuda_runtime.h>
#include <cuda_bf16.h>
#include <cstdint>

// Problem constants
#define BATCH 32
#define CIN   64
#define COUT  64
#define HH    112
#define WW    112
#define HW    (HH*WW)          // 12544
#define XS    80               // smem pixel / weight-row stride (bytes): bank-conflict-free & 16B aligned

// Repacked weights: [tap][cout][cin], tap = kh*3+kw, cin contiguous
__device__ __align__(16) int8_t g_wrep[9 * COUT * CIN];

// Inputs arrive as int32 (harness promotes int8 -> int32). Repack to int8.
__global__ void repack_w_kernel(const int* __restrict__ w) {
    int idx = blockIdx.x * blockDim.x + threadIdx.x;   // 9*64*64 = 36864
    if (idx < 9 * COUT * CIN) {
        int c   = idx & 63;
        int co  = (idx >> 6) & 63;
        int tap = idx >> 12;
        // w layout: [co][c][kh][kw] -> co*576 + c*9 + tap
        g_wrep[idx] = (int8_t)w[co * (CIN * 9) + c * 9 + tap];
    }
}

__device__ __forceinline__ void mma_s8(int* c, const uint32_t* a, uint32_t b0, uint32_t b1) {
    asm volatile(
        "mma.sync.aligned.m16n8k32.row.col.s32.s8.s8.s32 "
        "{%0,%1,%2,%3}, {%4,%5,%6,%7}, {%8,%9}, {%0,%1,%2,%3};\n"
        : "+r"(c[0]), "+r"(c[1]), "+r"(c[2]), "+r"(c[3])
        : "r"(a[0]), "r"(a[1]), "r"(a[2]), "r"(a[3]), "r"(b0), "r"(b1));
}

// SMEM layout:
//   sx: input tile, [4 rows][114 cols][XS]  (channels contiguous per pixel, 64 used of 80)
//   sw: weights,    [9 taps][64 couts][XS]  (channels contiguous per (tap,cout) row)
#define SX_BYTES (4 * 114 * XS)      // 36480
#define SW_BYTES (9 * COUT * XS)     // 46080
#define SMEM_BYTES (SX_BYTES + SW_BYTES)

__global__ __launch_bounds__(256, 2)
void conv_int8_kernel(const int* __restrict__ x,
                      const float* __restrict__ wscale,
                      const float* __restrict__ ascale,
                      const float* __restrict__ bias,
                      float* __restrict__ out) {
    extern __shared__ int8_t smem[];
    int8_t* sx = smem;
    int8_t* sw = smem + SX_BYTES;

    const int tid = threadIdx.x;
    const int b   = blockIdx.y;
    const int h0  = blockIdx.x * 2;      // 2 output rows per CTA

    // ---- zero the x tile (halo cols 0/113 and OOB rows must be zero) ----
    #pragma unroll 4
    for (int i = tid; i < SX_BYTES / 4; i += 256)
        reinterpret_cast<uint32_t*>(sx)[i] = 0;

    // ---- copy repacked weights (coalesced uint4) ----
    #pragma unroll
    for (int i = tid; i < 9 * COUT * 4; i += 256) {
        int row = i >> 2;
        reinterpret_cast<uint4*>(sw + row * XS)[i & 3] =
            reinterpret_cast<const uint4*>(g_wrep)[i];
    }
    __syncthreads();

    // ---- load input tile (int32 source), transpose to channel-contiguous int8 ----
    // units: tr(4 rows) x c4(16 channel-quads) x w4(28 col-quads); w4 fastest for coalescing
    for (int i = tid; i < 4 * 16 * 28; i += 256) {
        int w4 = i % 28;
        int c4 = (i / 28) & 15;
        int tr = i / (28 * 16);
        int g  = h0 - 1 + tr;
        uint4 u0 = {0,0,0,0}, u1 = {0,0,0,0}, u2 = {0,0,0,0}, u3 = {0,0,0,0};
        if ((unsigned)g < (unsigned)HH) {
            const int* px = x + ((size_t)b * CIN + c4 * 4) * HW + g * WW + w4 * 4;
            u0 = *reinterpret_cast<const uint4*>(px);
            u1 = *reinterpret_cast<const uint4*>(px + HW);
            u2 = *reinterpret_cast<const uint4*>(px + 2 * HW);
            u3 = *reinterpret_cast<const uint4*>(px + 3 * HW);
        }
        // ch-vectors: u0..u3 are channels c4*4..+3; components .x..w are pixels 0..3
        uint32_t p0[4] = {u0.x, u0.y, u0.z, u0.w};
        uint32_t p1[4] = {u1.x, u1.y, u1.z, u1.w};
        uint32_t p2[4] = {u2.x, u2.y, u2.z, u2.w};
        uint32_t p3[4] = {u3.x, u3.y, u3.z, u3.w};
        int8_t* dst = sx + (tr * 114 + 1 + w4 * 4) * XS + c4 * 4;
        #pragma unroll
        for (int j = 0; j < 4; ++j) {
            // low byte of each int32 is the int8 value (two's complement)
            uint32_t r01 = __byte_perm(p0[j], p1[j], 0x0040);   // [c,   c+1, -, -]
            uint32_t r23 = __byte_perm(p2[j], p3[j], 0x0040);   // [c+2, c+3, -, -]
            *reinterpret_cast<uint32_t*>(dst + j * XS) = __byte_perm(r01, r23, 0x5410);
        }
    }
    __syncthreads();

    // ---- compute: each warp = 32 couts x 56 pixels ----
    const int lane = tid & 31;
    const int warp = tid >> 5;
    const int wm   = warp >> 2;              // cout half: 0/1
    const int wn   = warp & 3;               // pixel quarter
    const int r    = wn >> 1;                // output row within CTA (0/1)
    const int colbase = (wn & 1) * 56;       // output col base
    const int co0  = wm * 32;
    const int g4   = lane >> 2;              // 0..7
    const int q4   = (lane & 3) * 4;         // channel byte offset within 16

    int acc[2][7][4];
    #pragma unroll
    for (int mt = 0; mt < 2; ++mt)
        #pragma unroll
        for (int nt = 0; nt < 7; ++nt)
            #pragma unroll
            for (int k = 0; k < 4; ++k)
                acc[mt][nt][k] = 0;

    #pragma unroll 1
    for (int tap = 0; tap < 9; ++tap) {
        const int8_t* sxp = sx + ((r + tap / 3) * 114 + colbase + (tap % 3)) * XS;
        const int8_t* swp = sw + tap * (COUT * XS) + (co0 + g4) * XS + q4;
        #pragma unroll
        for (int kh = 0; kh < 2; ++kh) {     // channels [0,32) / [32,64)
            const int ko = kh * 32;
            uint32_t a[2][4];
            #pragma unroll
            for (int mt = 0; mt < 2; ++mt) {
                const int8_t* ap = swp + mt * 16 * XS + ko;
                // PTX-standard A fragment order (row-block fastest):
                //   a0=(rows lo, k lo), a1=(rows hi, k lo),
                //   a2=(rows lo, k hi), a3=(rows hi, k hi)
                a[mt][0] = *reinterpret_cast<const uint32_t*>(ap);
                a[mt][1] = *reinterpret_cast<const uint32_t*>(ap + 8 * XS);
                a[mt][2] = *reinterpret_cast<const uint32_t*>(ap + 16);
                a[mt][3] = *reinterpret_cast<const uint32_t*>(ap + 8 * XS + 16);
            }
            #pragma unroll
            for (int nt = 0; nt < 7; ++nt) {
                const int8_t* bp = sxp + (nt * 8 + g4) * XS + q4 + ko;
                uint32_t b0 = *reinterpret_cast<const uint32_t*>(bp);
                uint32_t b1 = *reinterpret_cast<const uint32_t*>(bp + 16);
                mma_s8(acc[0][nt], a[0], b0, b1);
                mma_s8(acc[1][nt], a[1], b0, b1);
            }
        }
    }

    // ---- epilogue: dequant + bias, float2 stores ----
    const float scale = wscale[0] * ascale[0];
    const int h = h0 + r;
    #pragma unroll
    for (int mt = 0; mt < 2; ++mt) {
        const int co_a = co0 + mt * 16 + g4;
        const int co_b = co_a + 8;
        const float ba = bias[co_a];
        const float bb = bias[co_b];
        float* oa = out + (((size_t)b * COUT + co_a) * HH + h) * WW + colbase + (lane & 3) * 2;
        float* ob = out + (((size_t)b * COUT + co_b) * HH + h) * WW + colbase + (lane & 3) * 2;
        #pragma unroll
        for (int nt = 0; nt < 7; ++nt) {
            float2 va, vb;
            va.x = (float)acc[mt][nt][0] * scale + ba;
            va.y = (float)acc[mt][nt][1] * scale + ba;
            vb.x = (float)acc[mt][nt][2] * scale + bb;
            vb.y = (float)acc[mt][nt][3] * scale + bb;
            *reinterpret_cast<float2*>(oa + nt * 8) = va;
            *reinterpret_cast<float2*>(ob + nt * 8) = vb;
        }
    }
}

extern "C" void kernel_launch(void* const* d_in, const int* in_sizes, int n_in,
                              void* d_out, int out_size) {
    const int*   x    = reinterpret_cast<const int*>(d_in[0]);
    const int*   w    = reinterpret_cast<const int*>(d_in[1]);
    const float* ws   = reinterpret_cast<const float*>(d_in[2]);
    const float* as   = reinterpret_cast<const float*>(d_in[3]);
    const float* bias = reinterpret_cast<const float*>(d_in[4]);
    float* out = reinterpret_cast<float*>(d_out);

    repack_w_kernel<<<(9 * COUT * CIN + 255) / 256, 256>>>(w);

    cudaFuncSetAttribute(conv_int8_kernel,
                         cudaFuncAttributeMaxDynamicSharedMemorySize, SMEM_BYTES);
    dim3 grid(HH / 2, BATCH);   // 56 x 32 = 1792 CTAs
    conv_int8_kernel<<<grid, 256, SMEM_BYTES>>>(x, ws, as, bias, out);
}

// round 5
// speedup vs baseline: 1.2956x; 1.2956x over previous
#include <cuda_runtime.h>
#include <cuda_bf16.h>
#include <cstdint>

// Problem constants
#define BATCH 32
#define CIN   64
#define COUT  64
#define HH    112
#define WW    112
#define HW    (HH*WW)          // 12544
#define XS    80               // smem pixel / weight-row stride (bytes)

#define NTHREADS 384           // 8 IMMA warps + 4 dp4a warps
#define COLS_I   80            // IMMA covers cols [0,80), dp4a covers [80,112)

// Repacked weights: [tap][cout][cin], tap = kh*3+kw, cin contiguous
__device__ __align__(16) int8_t g_wrep[9 * COUT * CIN];

// Inputs arrive as int32 (harness promotes int8 -> int32). Repack to int8.
__global__ void repack_w_kernel(const int* __restrict__ w) {
    int idx = blockIdx.x * blockDim.x + threadIdx.x;   // 36864
    if (idx < 9 * COUT * CIN) {
        int c   = idx & 63;
        int co  = (idx >> 6) & 63;
        int tap = idx >> 12;
        g_wrep[idx] = (int8_t)w[co * (CIN * 9) + c * 9 + tap];
    }
}

__device__ __forceinline__ void mma_s8(int* c, const uint32_t* a, uint32_t b0, uint32_t b1) {
    asm volatile(
        "mma.sync.aligned.m16n8k32.row.col.s32.s8.s8.s32 "
        "{%0,%1,%2,%3}, {%4,%5,%6,%7}, {%8,%9}, {%0,%1,%2,%3};\n"
        : "+r"(c[0]), "+r"(c[1]), "+r"(c[2]), "+r"(c[3])
        : "r"(a[0]), "r"(a[1]), "r"(a[2]), "r"(a[3]), "r"(b0), "r"(b1));
}

#define SX_BYTES (4 * 114 * XS)      // 36480
#define SW_BYTES (9 * COUT * XS)     // 46080
#define SMEM_BYTES (SX_BYTES + SW_BYTES)

__global__ __launch_bounds__(NTHREADS, 2)
void conv_int8_kernel(const int* __restrict__ x,
                      const float* __restrict__ wscale,
                      const float* __restrict__ ascale,
                      const float* __restrict__ bias,
                      float* __restrict__ out) {
    extern __shared__ int8_t smem[];
    int8_t* sx = smem;
    int8_t* sw = smem + SX_BYTES;

    const int tid = threadIdx.x;
    const int b   = blockIdx.y;
    const int h0  = blockIdx.x * 2;      // 2 output rows per CTA

    // ---- zero the x tile (halo cols 0/113 and OOB rows must be zero) ----
    #pragma unroll 4
    for (int i = tid; i < SX_BYTES / 4; i += NTHREADS)
        reinterpret_cast<uint32_t*>(sx)[i] = 0;

    // ---- copy repacked weights ----
    #pragma unroll
    for (int i = tid; i < 9 * COUT * 4; i += NTHREADS) {
        int row = i >> 2;
        reinterpret_cast<uint4*>(sw + row * XS)[i & 3] =
            reinterpret_cast<const uint4*>(g_wrep)[i];
    }
    __syncthreads();

    // ---- load input tile (int32 source), transpose to channel-contiguous int8 ----
    for (int i = tid; i < 4 * 16 * 28; i += NTHREADS) {
        int w4 = i % 28;
        int c4 = (i / 28) & 15;
        int tr = i / (28 * 16);
        int g  = h0 - 1 + tr;
        uint4 u0 = {0,0,0,0}, u1 = {0,0,0,0}, u2 = {0,0,0,0}, u3 = {0,0,0,0};
        if ((unsigned)g < (unsigned)HH) {
            const int* px = x + ((size_t)b * CIN + c4 * 4) * HW + g * WW + w4 * 4;
            u0 = *reinterpret_cast<const uint4*>(px);
            u1 = *reinterpret_cast<const uint4*>(px + HW);
            u2 = *reinterpret_cast<const uint4*>(px + 2 * HW);
            u3 = *reinterpret_cast<const uint4*>(px + 3 * HW);
        }
        uint32_t p0[4] = {u0.x,u0.y,u0.z,u0.w}, p1[4] = {u1.x,u1.y,u1.z,u1.w},
                 p2[4] = {u2.x,u2.y,u2.z,u2.w}, p3[4] = {u3.x,u3.y,u3.z,u3.w};
        int8_t* dst = sx + (tr * 114 + 1 + w4 * 4) * XS + c4 * 4;
        #pragma unroll
        for (int j = 0; j < 4; ++j) {
            uint32_t r01 = __byte_perm(p0[j], p1[j], 0x0040);
            uint32_t r23 = __byte_perm(p2[j], p3[j], 0x0040);
            *reinterpret_cast<uint32_t*>(dst + j * XS) = __byte_perm(r01, r23, 0x5410);
        }
    }
    __syncthreads();

    const int lane  = tid & 31;
    const int warp  = tid >> 5;
    const float scale = wscale[0] * ascale[0];

    if (warp < 8) {
        // ================= IMMA warps: cols [0, 80) =================
        const int wm   = warp >> 2;              // cout half
        const int wn   = warp & 3;
        const int r    = wn >> 1;                // output row within CTA
        const int colbase = (wn & 1) * (COLS_I / 2);
        const int co0  = wm * 32;
        const int g4   = lane >> 2;              // 0..7
        const int q4   = (lane & 3) * 4;

        int acc[2][5][4];
        #pragma unroll
        for (int mt = 0; mt < 2; ++mt)
            #pragma unroll
            for (int nt = 0; nt < 5; ++nt)
                #pragma unroll
                for (int k = 0; k < 4; ++k)
                    acc[mt][nt][k] = 0;

        #pragma unroll 1
        for (int tap = 0; tap < 9; ++tap) {
            const int8_t* sxp = sx + ((r + tap / 3) * 114 + colbase + (tap % 3)) * XS;
            const int8_t* swp = sw + tap * (COUT * XS) + (co0 + g4) * XS + q4;
            #pragma unroll
            for (int kh = 0; kh < 2; ++kh) {     // channels [0,32)/[32,64)
                const int ko = kh * 32;
                uint32_t a[2][4];
                #pragma unroll
                for (int mt = 0; mt < 2; ++mt) {
                    const int8_t* ap = swp + mt * 16 * XS + ko;
                    a[mt][0] = *reinterpret_cast<const uint32_t*>(ap);
                    a[mt][1] = *reinterpret_cast<const uint32_t*>(ap + 8 * XS);
                    a[mt][2] = *reinterpret_cast<const uint32_t*>(ap + 16);
                    a[mt][3] = *reinterpret_cast<const uint32_t*>(ap + 8 * XS + 16);
                }
                #pragma unroll
                for (int nt = 0; nt < 5; ++nt) {
                    const int8_t* bp = sxp + (nt * 8 + g4) * XS + q4 + ko;
                    uint32_t b0 = *reinterpret_cast<const uint32_t*>(bp);
                    uint32_t b1 = *reinterpret_cast<const uint32_t*>(bp + 16);
                    mma_s8(acc[0][nt], a[0], b0, b1);
                    mma_s8(acc[1][nt], a[1], b0, b1);
                }
            }
        }

        const int h = h0 + r;
        #pragma unroll
        for (int mt = 0; mt < 2; ++mt) {
            const int co_a = co0 + mt * 16 + g4;
            const int co_b = co_a + 8;
            const float ba = bias[co_a];
            const float bb = bias[co_b];
            float* oa = out + (((size_t)b * COUT + co_a) * HH + h) * WW + colbase + (lane & 3) * 2;
            float* ob = out + (((size_t)b * COUT + co_b) * HH + h) * WW + colbase + (lane & 3) * 2;
            #pragma unroll
            for (int nt = 0; nt < 5; ++nt) {
                float2 va, vb;
                va.x = (float)acc[mt][nt][0] * scale + ba;
                va.y = (float)acc[mt][nt][1] * scale + ba;
                vb.x = (float)acc[mt][nt][2] * scale + bb;
                vb.y = (float)acc[mt][nt][3] * scale + bb;
                *reinterpret_cast<float2*>(oa + nt * 8) = va;
                *reinterpret_cast<float2*>(ob + nt * 8) = vb;
            }
        }
    } else {
        // ================= dp4a warps: cols [80, 112) =================
        const int wid2   = warp - 8;             // 0..3
        const int r      = wid2 & 1;             // output row within CTA
        const int cohalf = wid2 >> 1;            // cout half
        const int g      = lane >> 3;            // 0..3  (co offset)
        const int pj     = lane & 7;             // 0..7  (px group)
        const int co0    = cohalf * 32 + g;      // thread co = co0 + 4*i
        const int px0    = COLS_I + pj;          // thread px = px0 + 8*j

        int acc[8][4];
        #pragma unroll
        for (int i = 0; i < 8; ++i)
            #pragma unroll
            for (int j = 0; j < 4; ++j)
                acc[i][j] = 0;

        #pragma unroll 1
        for (int tap = 0; tap < 9; ++tap) {
            const int dh = tap / 3, dw = tap - dh * 3;
            const int8_t* xp = sx + ((r + dh) * 114 + px0 + dw) * XS;
            const int8_t* wp = sw + tap * (COUT * XS) + co0 * XS;
            #pragma unroll 4
            for (int kw = 0; kw < 16; ++kw) {
                int wv[8], xv[4];
                #pragma unroll
                for (int i = 0; i < 8; ++i)
                    wv[i] = *reinterpret_cast<const int*>(wp + i * 4 * XS + kw * 4);
                #pragma unroll
                for (int j = 0; j < 4; ++j)
                    xv[j] = *reinterpret_cast<const int*>(xp + j * 8 * XS + kw * 4);
                #pragma unroll
                for (int i = 0; i < 8; ++i)
                    #pragma unroll
                    for (int j = 0; j < 4; ++j)
                        acc[i][j] = __dp4a(wv[i], xv[j], acc[i][j]);
            }
        }

        const int h = h0 + r;
        #pragma unroll
        for (int i = 0; i < 8; ++i) {
            const int co = co0 + 4 * i;
            const float bc = bias[co];
            float* op = out + (((size_t)b * COUT + co) * HH + h) * WW;
            #pragma unroll
            for (int j = 0; j < 4; ++j)
                op[px0 + 8 * j] = (float)acc[i][j] * scale + bc;
        }
    }
}

extern "C" void kernel_launch(void* const* d_in, const int* in_sizes, int n_in,
                              void* d_out, int out_size) {
    const int*   x    = reinterpret_cast<const int*>(d_in[0]);
    const int*   w    = reinterpret_cast<const int*>(d_in[1]);
    const float* ws   = reinterpret_cast<const float*>(d_in[2]);
    const float* as   = reinterpret_cast<const float*>(d_in[3]);
    const float* bias = reinterpret_cast<const float*>(d_in[4]);
    float* out = reinterpret_cast<float*>(d_out);

    repack_w_kernel<<<(9 * COUT * CIN + 255) / 256, 256>>>(w);

    cudaFuncSetAttribute(conv_int8_kernel,
                         cudaFuncAttributeMaxDynamicSharedMemorySize, SMEM_BYTES);
    dim3 grid(HH / 2, BATCH);   // 56 x 32 = 1792 CTAs
    conv_int8_kernel<<<grid, NTHREADS, SMEM_BYTES>>>(x, ws, as, bias, out);
}